// round 1
// baseline (speedup 1.0000x reference)
#include <cuda_runtime.h>

// Problem constants
#define S_LEN   64
#define D_MODEL 768
#define D_FFN   3072
#define RANK    16
#define MOD_SCALE 0.1f

// Scratch for modulation (64 x 16) — device global, no allocation.
__device__ float g_mod[S_LEN * RANK];

// ---------------------------------------------------------------------------
// Kernel 1: modulation[s][r] = 0.1 * tanh( sum_d attn[s][d] * A[d][r] )
// Tiny: 1024 outputs, dot length 768. One block per s, 16 threads (one per r).
// attn row is broadcast-read (L1 hit after first), A reads coalesced per d.
// ---------------------------------------------------------------------------
__global__ void mod_kernel(const float* __restrict__ attn,
                           const float* __restrict__ A)
{
    const int s = blockIdx.x;
    const int r = threadIdx.x;   // 0..15
    const float* arow = attn + (size_t)s * D_MODEL;
    float acc = 0.0f;
#pragma unroll 8
    for (int d = 0; d < D_MODEL; d++) {
        acc += arow[d] * A[d * RANK + r];
    }
    g_mod[s * RANK + r] = MOD_SCALE * tanhf(acc);
}

// ---------------------------------------------------------------------------
// Kernel 2: delta_w[p][f] = sum_r C[p][r] * B[r][f],  p = s*768 + d,
//           C[p][r] = mod[s][r] * A[d][r]
//
// Block: 256 threads. Each thread owns 4 consecutive f (one float4 store),
// so a block covers an f-tile of 1024. B slab for the tile is held in
// REGISTERS (16 x float4 = 64 regs/thread) — the hot loop touches only
// smem-broadcast C values and does 64 FFMA + 1 STG.128 per pair.
//
// Grid: x = 384 pair-chunks (128 pairs each, 49152 total, exact),
//       y = 3 f-tiles (3*1024 = 3072, exact).
// ---------------------------------------------------------------------------
#define FTILE       1024
#define PAIRS_PER_B 128
#define THREADS     256

__global__ __launch_bounds__(THREADS)
void deltaw_kernel(const float* __restrict__ A,
                   const float* __restrict__ B,
                   float* __restrict__ out)
{
    const int f0    = blockIdx.y * FTILE + threadIdx.x * 4;
    const int pair0 = blockIdx.x * PAIRS_PER_B;

    // Load this thread's B slab into registers: B[r][f0..f0+3]
    float4 Breg[RANK];
#pragma unroll
    for (int r = 0; r < RANK; r++) {
        Breg[r] = *reinterpret_cast<const float4*>(&B[r * D_FFN + f0]);
    }

    // Cooperatively build C[p][r] = mod[s][r] * A[d][r] for this pair chunk.
    __shared__ float Cs[PAIRS_PER_B][RANK];
    for (int i = threadIdx.x; i < PAIRS_PER_B * RANK; i += THREADS) {
        const int p  = i / RANK;
        const int r  = i % RANK;
        const int pd = pair0 + p;
        const int s  = pd / D_MODEL;
        const int d  = pd % D_MODEL;
        Cs[p][r] = g_mod[s * RANK + r] * A[d * RANK + r];
    }
    __syncthreads();

    // Hot loop: for each pair, 64 FFMA from register-resident B and
    // smem-broadcast C, then one coalesced 16B store.
    float* outp = out + (size_t)pair0 * D_FFN + f0;
#pragma unroll 2
    for (int p = 0; p < PAIRS_PER_B; p++) {
        float4 acc = make_float4(0.f, 0.f, 0.f, 0.f);
#pragma unroll
        for (int r = 0; r < RANK; r++) {
            const float c = Cs[p][r];
            acc.x += c * Breg[r].x;
            acc.y += c * Breg[r].y;
            acc.z += c * Breg[r].z;
            acc.w += c * Breg[r].w;
        }
        *reinterpret_cast<float4*>(outp) = acc;
        outp += D_FFN;
    }
}

// ---------------------------------------------------------------------------
// Launch
// ---------------------------------------------------------------------------
extern "C" void kernel_launch(void* const* d_in, const int* in_sizes, int n_in,
                              void* d_out, int out_size)
{
    const float* attn = (const float*)d_in[0];  // (1, 64, 768)
    const float* A    = (const float*)d_in[1];  // (768, 16)
    const float* B    = (const float*)d_in[2];  // (16, 3072)
    float* out        = (float*)d_out;          // (1, 64, 768, 3072)

    mod_kernel<<<S_LEN, RANK>>>(attn, A);

    dim3 grid((S_LEN * D_MODEL) / PAIRS_PER_B,  // 384
              D_FFN / FTILE);                   // 3
    deltaw_kernel<<<grid, THREADS>>>(A, B, out);
}

// round 2
// speedup vs baseline: 1.3524x; 1.3524x over previous
#include <cuda_runtime.h>
#include <cstdint>

// Problem constants
#define S_LEN   64
#define D_MODEL 768
#define D_FFN   3072
#define RANK    16
#define MOD_SCALE 0.1f

// Packed f32x2 FMA: d = a*b + c on two lanes (sm_103a fast path; ptxas won't
// auto-fuse this from C++).
#define FMA_F32X2(d, a, b, c) \
    asm("fma.rn.f32x2 %0, %1, %2, %3;" : "=l"(d) : "l"(a), "l"(b), "l"(c))

// Scratch for modulation (64 x 16) — device global, no allocation.
__device__ float g_mod[S_LEN * RANK];

// ---------------------------------------------------------------------------
// Kernel 1: modulation[s][r] = 0.1 * tanh( sum_d attn[s][d] * A[d][r] )
// One block per s, 256 threads: thread = (chunk, r), 16 chunks x 48 d each,
// then a 16-way combine in smem. Latency ~ 48-iter loop + reduce.
// ---------------------------------------------------------------------------
__global__ __launch_bounds__(256)
void mod_kernel(const float* __restrict__ attn,
                const float* __restrict__ A)
{
    const int s     = blockIdx.x;
    const int r     = threadIdx.x & 15;
    const int chunk = threadIdx.x >> 4;          // 0..15
    const int d0    = chunk * (D_MODEL / 16);    // 48 d per chunk

    const float* arow = attn + (size_t)s * D_MODEL;
    float acc = 0.0f;
#pragma unroll 4
    for (int d = d0; d < d0 + (D_MODEL / 16); d++) {
        acc += arow[d] * A[d * RANK + r];
    }

    __shared__ float part[16][RANK];
    part[chunk][r] = acc;
    __syncthreads();

    if (threadIdx.x < RANK) {
        float t = 0.0f;
#pragma unroll
        for (int c = 0; c < 16; c++) t += part[c][threadIdx.x];
        g_mod[s * RANK + threadIdx.x] = MOD_SCALE * tanhf(t);
    }
}

// ---------------------------------------------------------------------------
// Kernel 2: delta_w[p][f] = sum_r C[p][r] * B[r][f],  p = s*768 + d,
//           C[p][r] = mod[s][r] * A[d][r]
//
// Per-pair inner work per thread: 8x LDS.128 (broadcast, pre-duplicated
// {c,c} pairs) + 32x FFMA2 (packed f32x2) + 1x STG.128 streaming store.
// B slab (16 x float4) register-resident.
// ---------------------------------------------------------------------------
#define FTILE       1024
#define PAIRS_PER_B 128
#define THREADS     256

__global__ __launch_bounds__(THREADS)
void deltaw_kernel(const float* __restrict__ A,
                   const float* __restrict__ B,
                   float* __restrict__ out)
{
    const int f0    = blockIdx.y * FTILE + threadIdx.x * 4;
    const int pair0 = blockIdx.x * PAIRS_PER_B;

    // B slab in registers as packed f32x2 halves: Breg[r] = {B[r][f0..1], B[r][f0+2..3]}
    ulonglong2 Breg[RANK];
#pragma unroll
    for (int r = 0; r < RANK; r++) {
        Breg[r] = *reinterpret_cast<const ulonglong2*>(&B[r * D_FFN + f0]);
    }

    // C duplicated for packed math: Cs[p][r] = {c, c} (float2).
    // Layout per pair: c0,c0,c1,c1,...,c15,c15  -> 8 float4 loads per pair.
    __shared__ float2 Cs[PAIRS_PER_B][RANK];
    for (int i = threadIdx.x; i < PAIRS_PER_B * RANK; i += THREADS) {
        const int p  = i >> 4;
        const int r  = i & 15;
        const int pd = pair0 + p;
        const int s  = pd / D_MODEL;
        const int d  = pd % D_MODEL;
        const float c = g_mod[s * RANK + r] * A[d * RANK + r];
        Cs[p][r] = make_float2(c, c);
    }
    __syncthreads();

    float* outp = out + (size_t)pair0 * D_FFN + f0;
#pragma unroll 2
    for (int p = 0; p < PAIRS_PER_B; p++) {
        const ulonglong2* cp = reinterpret_cast<const ulonglong2*>(&Cs[p][0]);
        uint64_t a0 = 0ull;   // packed {0.f, 0.f} accum for f0..f0+1
        uint64_t a1 = 0ull;   // packed accum for f0+2..f0+3
#pragma unroll
        for (int i = 0; i < 8; i++) {
            const ulonglong2 cc = cp[i];     // {c2i,c2i},{c2i+1,c2i+1} via one LDS.128
            FMA_F32X2(a0, cc.x, Breg[2 * i].x,     a0);
            FMA_F32X2(a1, cc.x, Breg[2 * i].y,     a1);
            FMA_F32X2(a0, cc.y, Breg[2 * i + 1].x, a0);
            FMA_F32X2(a1, cc.y, Breg[2 * i + 1].y, a1);
        }
        float4 v;
        v.x = __uint_as_float((uint32_t)(a0 & 0xFFFFFFFFull));
        v.y = __uint_as_float((uint32_t)(a0 >> 32));
        v.z = __uint_as_float((uint32_t)(a1 & 0xFFFFFFFFull));
        v.w = __uint_as_float((uint32_t)(a1 >> 32));
        __stcs(reinterpret_cast<float4*>(outp), v);   // streaming store hint
        outp += D_FFN;
    }
}

// ---------------------------------------------------------------------------
// Launch
// ---------------------------------------------------------------------------
extern "C" void kernel_launch(void* const* d_in, const int* in_sizes, int n_in,
                              void* d_out, int out_size)
{
    const float* attn = (const float*)d_in[0];  // (1, 64, 768)
    const float* A    = (const float*)d_in[1];  // (768, 16)
    const float* B    = (const float*)d_in[2];  // (16, 3072)
    float* out        = (float*)d_out;          // (1, 64, 768, 3072)

    mod_kernel<<<S_LEN, 256>>>(attn, A);

    dim3 grid((S_LEN * D_MODEL) / PAIRS_PER_B,  // 384
              D_FFN / FTILE);                   // 3
    deltaw_kernel<<<grid, THREADS>>>(A, B, out);
}